// round 7
// baseline (speedup 1.0000x reference)
#include <cuda_runtime.h>
#include <cstdint>

// ---------------------------------------------------------------------------
// Router: r[b,e] = || W[e] @ x[b] ||_2
//   x: [8192, 4096] f32, W: [16, 64, 4096] f32 (row-major), out: [8192,16] f32
// GEMM C[8192,1024] = X @ W^T via legacy mma.sync.m16n8k8.tf32 (base sm_103:
// tcgen05 rejected by this build's ptxas).
// R7 changes vs R6 (499.9us):
//  * inputs pre-rounded to tf32 (cvt.rna) into __device__ scratch -> zero CVT
//    in the mainloop, unbiased truncation (rel_err ~4e-5).
//  * k-slot remap: MMA instance ks consumes global cols {8t+2ks, 8t+2ks+1};
//    thread quad q supplies cols 8q+2ks(+1) for BOTH A and B. Thread fragment
//    data for 2 k-steps is then a contiguous float4 -> LDS.128 fragment loads
//    (32/kt) instead of LDS.32 (128/kt). SMEM tiles stay raw (cp.async as-is).
// ---------------------------------------------------------------------------

#define BDIM   8192
#define DDIM   4096
#define EDIM   16
#define NTOT   1024
#define BM     128
#define BN     256
#define BK     32
#define STAGES 3
#define KT     (DDIM / BK)             /* 128 */
#define LDA    (BK + 4)                /* 36 floats; rows 16B-aligned (144B) */
#define A_STG  (BM * LDA)              /* 4608 floats */
#define B_STG  (BN * LDA)              /* 9216 floats */
#define SMEM_BYTES (STAGES * (A_STG + B_STG) * 4)   /* 165888 */

// tf32-rounded scratch copies (module-scope __device__: sanctioned scratch)
__device__ float g_xr[(size_t)BDIM * DDIM];   // 134 MB
__device__ float g_wr[(size_t)NTOT * DDIM];   //  17 MB

__device__ __forceinline__ void mma_tf32(float c[4],
                                         uint32_t a0, uint32_t a1,
                                         uint32_t a2, uint32_t a3,
                                         uint32_t b0, uint32_t b1) {
    asm volatile(
        "mma.sync.aligned.m16n8k8.row.col.f32.tf32.tf32.f32 "
        "{%0,%1,%2,%3}, {%4,%5,%6,%7}, {%8,%9}, {%0,%1,%2,%3};"
        : "+f"(c[0]), "+f"(c[1]), "+f"(c[2]), "+f"(c[3])
        : "r"(a0), "r"(a1), "r"(a2), "r"(a3), "r"(b0), "r"(b1));
}

__device__ __forceinline__ void cp16(uint32_t dst, const float* src) {
    asm volatile("cp.async.cg.shared.global [%0], [%1], 16;"
                 :: "r"(dst), "l"(src) : "memory");
}

__device__ __forceinline__ uint32_t fu(float f) { return __float_as_uint(f); }

// ---------------------------------------------------------------------------
// Prep: round inputs to tf32 (RNA -> unbiased) into scratch
// ---------------------------------------------------------------------------
__global__ void prep_round_x(const float4* __restrict__ src) {
    size_t i = (size_t)blockIdx.x * blockDim.x + threadIdx.x;
    float4 v = src[i];
    uint4 o;
    asm("cvt.rna.tf32.f32 %0, %1;" : "=r"(o.x) : "f"(v.x));
    asm("cvt.rna.tf32.f32 %0, %1;" : "=r"(o.y) : "f"(v.y));
    asm("cvt.rna.tf32.f32 %0, %1;" : "=r"(o.z) : "f"(v.z));
    asm("cvt.rna.tf32.f32 %0, %1;" : "=r"(o.w) : "f"(v.w));
    reinterpret_cast<uint4*>(g_xr)[i] = o;
}

__global__ void prep_round_w(const float4* __restrict__ src) {
    size_t i = (size_t)blockIdx.x * blockDim.x + threadIdx.x;
    float4 v = src[i];
    uint4 o;
    asm("cvt.rna.tf32.f32 %0, %1;" : "=r"(o.x) : "f"(v.x));
    asm("cvt.rna.tf32.f32 %0, %1;" : "=r"(o.y) : "f"(v.y));
    asm("cvt.rna.tf32.f32 %0, %1;" : "=r"(o.z) : "f"(v.z));
    asm("cvt.rna.tf32.f32 %0, %1;" : "=r"(o.w) : "f"(v.w));
    reinterpret_cast<uint4*>(g_wr)[i] = o;
}

// ---------------------------------------------------------------------------
// grid = (NTOT/BN = 4, BDIM/BM = 64); n fastest -> 4 n-tiles of an m-tile
// co-resident (A fetched from DRAM once). 8 warps: 2(m) x 4(n), warp tile
// 64x64 = one expert per warp.
// ---------------------------------------------------------------------------
__global__ __launch_bounds__(256, 1)
void router_kernel(float* __restrict__ out) {
    extern __shared__ float smem[];
    float* As = smem;                       // [STAGES][BM][LDA]
    float* Bs = smem + STAGES * A_STG;      // [STAGES][BN][LDA]

    const int tid  = threadIdx.x;
    const int lane = tid & 31;
    const int wid  = tid >> 5;
    const int wm   = wid & 1;
    const int wn   = wid >> 1;

    const int m_base = blockIdx.y * BM;
    const int n_base = blockIdx.x * BN;

    // ---- cp.async producer: thread -> (row = tid/8, 16B chunk = tid%8) ----
    const int lrow = tid >> 3;
    const int lch  = tid & 7;
    const float* gA = g_xr + (size_t)(m_base + lrow) * DDIM + lch * 4;
    const float* gB = g_wr + (size_t)(n_base + lrow) * DDIM + lch * 4;
    const uint32_t sA0 = (uint32_t)__cvta_generic_to_shared(As)
                       + (uint32_t)(lrow * LDA + lch * 4) * 4u;
    const uint32_t sB0 = (uint32_t)__cvta_generic_to_shared(Bs)
                       + (uint32_t)(lrow * LDA + lch * 4) * 4u;

    auto load_stage = [&](int s, int k0) {
        const uint32_t a = sA0 + (uint32_t)(s * A_STG) * 4u;
        const float* ga = gA + k0;
#pragma unroll
        for (int p = 0; p < BM / 32; ++p)
            cp16(a + (uint32_t)(p * 32 * LDA) * 4u, ga + (size_t)(p * 32) * DDIM);
        const uint32_t b = sB0 + (uint32_t)(s * B_STG) * 4u;
        const float* gb = gB + k0;
#pragma unroll
        for (int p = 0; p < BN / 32; ++p)
            cp16(b + (uint32_t)(p * 32 * LDA) * 4u, gb + (size_t)(p * 32) * DDIM);
    };

#pragma unroll
    for (int s = 0; s < STAGES - 1; ++s) {
        load_stage(s, s * BK);
        asm volatile("cp.async.commit_group;" ::: "memory");
    }

    float acc[4][8][4];
#pragma unroll
    for (int mt = 0; mt < 4; ++mt)
#pragma unroll
        for (int nt = 0; nt < 8; ++nt)
#pragma unroll
            for (int i = 0; i < 4; ++i) acc[mt][nt][i] = 0.f;

    const float* Aw = As + wm * 64 * LDA;
    const float* Bw = Bs + wn * 64 * LDA;
    const int g = lane >> 2;                 // group (row) id
    const int q = lane & 3;                  // quad id

#pragma unroll 1
    for (int kt = 0; kt < KT; ++kt) {
        asm volatile("cp.async.wait_group %0;" :: "n"(STAGES - 2) : "memory");
        __syncthreads();

        const int pf = kt + STAGES - 1;
        if (pf < KT) load_stage(pf % STAGES, pf * BK);
        asm volatile("cp.async.commit_group;" ::: "memory");

        const int cur = kt % STAGES;
        const float* Ac = Aw + cur * A_STG;
        const float* Bc = Bw + cur * B_STG;

        // Two halves; each half's float4 carries 2 k-steps of fragment data.
        // Thread quad q owns global cols {8q+2ks, 8q+2ks+1} (same map A & B).
#pragma unroll
        for (int h2 = 0; h2 < 2; ++h2) {
            const int co = 8 * q + 4 * h2;           // 16B aligned
            float4 al[4], ah[4];                     // A rows g, g+8 per mt
#pragma unroll
            for (int mt = 0; mt < 4; ++mt) {
                const float* p = Ac + (mt * 16 + g) * LDA + co;
                al[mt] = *reinterpret_cast<const float4*>(p);
                ah[mt] = *reinterpret_cast<const float4*>(p + 8 * LDA);
            }
            float4 bv[8];
#pragma unroll
            for (int nt = 0; nt < 8; ++nt)
                bv[nt] = *reinterpret_cast<const float4*>(
                             Bc + (nt * 8 + g) * LDA + co);

            // pass 1: ks = 2*h2   (x/y lanes) — 32 independent acc chains
#pragma unroll
            for (int mt = 0; mt < 4; ++mt)
#pragma unroll
                for (int nt = 0; nt < 8; ++nt)
                    mma_tf32(acc[mt][nt],
                             fu(al[mt].x), fu(ah[mt].x), fu(al[mt].y), fu(ah[mt].y),
                             fu(bv[nt].x), fu(bv[nt].y));
            // pass 2: ks = 2*h2+1 (z/w lanes)
#pragma unroll
            for (int mt = 0; mt < 4; ++mt)
#pragma unroll
                for (int nt = 0; nt < 8; ++nt)
                    mma_tf32(acc[mt][nt],
                             fu(al[mt].z), fu(ah[mt].z), fu(al[mt].w), fu(ah[mt].w),
                             fu(bv[nt].z), fu(bv[nt].w));
        }
    }

    // ---- epilogue: ||.||_2 over this warp's 64 n-cols (one expert) --------
    const int e = blockIdx.x * (BN / 64) + wn;
#pragma unroll
    for (int mt = 0; mt < 4; ++mt) {
        float s0 = 0.f, s1 = 0.f;
#pragma unroll
        for (int nt = 0; nt < 8; ++nt) {
            s0 = fmaf(acc[mt][nt][0], acc[mt][nt][0], s0);
            s0 = fmaf(acc[mt][nt][1], acc[mt][nt][1], s0);
            s1 = fmaf(acc[mt][nt][2], acc[mt][nt][2], s1);
            s1 = fmaf(acc[mt][nt][3], acc[mt][nt][3], s1);
        }
        s0 += __shfl_xor_sync(0xffffffffu, s0, 1);
        s0 += __shfl_xor_sync(0xffffffffu, s0, 2);
        s1 += __shfl_xor_sync(0xffffffffu, s1, 1);
        s1 += __shfl_xor_sync(0xffffffffu, s1, 2);
        if ((lane & 3) == 0) {
            const int row = m_base + wm * 64 + mt * 16 + g;
            out[(size_t)row * EDIM + e]       = sqrtf(s0);
            out[(size_t)(row + 8) * EDIM + e] = sqrtf(s1);
        }
    }
}

// ---------------------------------------------------------------------------
extern "C" void kernel_launch(void* const* d_in, const int* in_sizes, int n_in,
                              void* d_out, int out_size) {
    (void)in_sizes; (void)n_in; (void)out_size;
    const float* x = (const float*)d_in[0];   // [8192, 4096]
    const float* w = (const float*)d_in[1];   // [16, 64, 4096] == [1024, 4096]
    float* out = (float*)d_out;               // [8192, 16]

    prep_round_x<<<(BDIM * DDIM / 4) / 256, 256>>>((const float4*)x);
    prep_round_w<<<(NTOT * DDIM / 4) / 256, 256>>>((const float4*)w);

    cudaFuncSetAttribute(router_kernel,
                         cudaFuncAttributeMaxDynamicSharedMemorySize, SMEM_BYTES);
    router_kernel<<<dim3(NTOT / BN, BDIM / BM), 256, SMEM_BYTES>>>(out);
}